// round 6
// baseline (speedup 1.0000x reference)
#include <cuda_runtime.h>
#include <math.h>

// Problem constants (shapes fixed by the reference)
#define BB    4
#define SS    16
#define DIMM  4096
#define NHH   32
#define NKVV  8
#define HDD   128
#define MAXPP 4096
#define STARTP 2048
#define LCTX  2064   // STARTP + SS
#define SPLITK 16
#define KCHUNK (DIMM / SPLITK)   // 256 -> 16 BK=16 iterations per block

typedef unsigned long long ull;

// ---------------------------------------------------------------------------
// Packed f32x2 helpers (B300 FFMA2 path — only reachable via explicit PTX)
// ---------------------------------------------------------------------------
__device__ __forceinline__ ull pack2(float lo, float hi) {
    ull r; asm("mov.b64 %0, {%1, %2};" : "=l"(r) : "f"(lo), "f"(hi)); return r;
}
__device__ __forceinline__ void ffma2(ull &d, ull a, ull b) {
    asm("fma.rn.f32x2 %0, %1, %2, %0;" : "+l"(d) : "l"(a), "l"(b));
}
__device__ __forceinline__ void unpack2(ull v, float &lo, float &hi) {
    asm("mov.b64 {%0, %1}, %2;" : "=f"(lo), "=f"(hi) : "l"(v));
}

// ---------------------------------------------------------------------------
// Device scratch (no allocations allowed)
// ---------------------------------------------------------------------------
__device__ float g_q[BB*SS*NHH*HDD];        // row=(b*16+s), col=h*128+d
__device__ float g_k[BB*SS*NKVV*HDD];       // row=(b*16+s), col=kvh*128+d
__device__ float g_v[BB*SS*NKVV*HDD];
__device__ float g_scores[(size_t)BB*NHH*SS*LCTX]; // ~17MB
__device__ float g_attn[BB*SS*NHH*HDD];     // row=(b*16+s), col=h*128+d

// ---------------------------------------------------------------------------
// Zero scratch + output (GEMM/PV accumulate with atomics)
// ---------------------------------------------------------------------------
__global__ void zero_kernel(float* __restrict__ dout) {
    int i = blockIdx.x * blockDim.x + threadIdx.x;   // grid covers 262144
    if (i < BB*SS*NHH*HDD) { g_q[i] = 0.f; g_attn[i] = 0.f; dout[i] = 0.f; }
    if (i < BB*SS*NKVV*HDD) { g_k[i] = 0.f; g_v[i] = 0.f; }
}

// ---------------------------------------------------------------------------
// Tiled fp32 GEMM with split-K=16, register double-buffering, FFMA2.
// C[64 x N] += A[64 x 4096] * W[4096 x N]
// mode 0: fused QKV (bx<32 -> Wq->g_q, bx<40 -> Wk->g_k, else Wv->g_v), A=x
// mode 1: Wo -> d_out, A=g_attn
// ---------------------------------------------------------------------------
__global__ __launch_bounds__(256) void gemm64(
    const float* __restrict__ Aext,
    const float* __restrict__ W0, const float* __restrict__ W1,
    const float* __restrict__ W2,
    float* __restrict__ Cout, int mode)
{
    const float* A; const float* W; float* C; int N, n0;
    const int bx = blockIdx.x;
    if (mode == 0) {
        A = Aext;
        if (bx < 32)      { W = W0; C = g_q; N = 4096; n0 = bx * 128; }
        else if (bx < 40) { W = W1; C = g_k; N = 1024; n0 = (bx - 32) * 128; }
        else              { W = W2; C = g_v; N = 1024; n0 = (bx - 40) * 128; }
    } else {
        A = g_attn; W = W0; C = Cout; N = 4096; n0 = bx * 128;
    }
    const int k0 = blockIdx.y * KCHUNK;

    __shared__ float As[16][64];
    __shared__ float Bs[16][128];

    const int t  = threadIdx.x;
    const int tx = t & 15, ty = t >> 4;
    const int arow = t >> 2, akq = t & 3;
    const int f0 = t * 2, f1 = t * 2 + 1;
    const int kr0 = f0 >> 5, nq0 = f0 & 31;
    const int kr1 = f1 >> 5, nq1 = f1 & 31;

    ull acc2[4][4];
    #pragma unroll
    for (int i = 0; i < 4; i++)
        #pragma unroll
        for (int j = 0; j < 4; j++) acc2[i][j] = 0ull;

    // Prologue: preload first tile into registers
    float4 aN = *(const float4*)(A + (size_t)arow * DIMM + k0 + akq * 4);
    float4 bN0 = *(const float4*)(W + (size_t)(k0 + kr0) * N + n0 + nq0 * 4);
    float4 bN1 = *(const float4*)(W + (size_t)(k0 + kr1) * N + n0 + nq1 * 4);

    #pragma unroll 1
    for (int it = 0; it < KCHUNK / 16; it++) {
        As[akq*4+0][arow] = aN.x;
        As[akq*4+1][arow] = aN.y;
        As[akq*4+2][arow] = aN.z;
        As[akq*4+3][arow] = aN.w;
        *(float4*)&Bs[kr0][nq0*4] = bN0;
        *(float4*)&Bs[kr1][nq1*4] = bN1;
        __syncthreads();

        if (it + 1 < KCHUNK / 16) {   // overlap next tile's gmem loads with compute
            const int kk = k0 + (it + 1) * 16;
            aN  = *(const float4*)(A + (size_t)arow * DIMM + kk + akq * 4);
            bN0 = *(const float4*)(W + (size_t)(kk + kr0) * N + n0 + nq0 * 4);
            bN1 = *(const float4*)(W + (size_t)(kk + kr1) * N + n0 + nq1 * 4);
        }

        #pragma unroll
        for (int k = 0; k < 16; k++) {
            float4 a  = *(const float4*)&As[k][ty*4];
            float4 b0 = *(const float4*)&Bs[k][tx*8];
            float4 b1 = *(const float4*)&Bs[k][tx*8+4];
            ull bp0 = pack2(b0.x, b0.y), bp1 = pack2(b0.z, b0.w);
            ull bp2 = pack2(b1.x, b1.y), bp3 = pack2(b1.z, b1.w);
            ull ap0 = pack2(a.x, a.x), ap1 = pack2(a.y, a.y);
            ull ap2 = pack2(a.z, a.z), ap3 = pack2(a.w, a.w);
            ffma2(acc2[0][0], ap0, bp0); ffma2(acc2[0][1], ap0, bp1);
            ffma2(acc2[0][2], ap0, bp2); ffma2(acc2[0][3], ap0, bp3);
            ffma2(acc2[1][0], ap1, bp0); ffma2(acc2[1][1], ap1, bp1);
            ffma2(acc2[1][2], ap1, bp2); ffma2(acc2[1][3], ap1, bp3);
            ffma2(acc2[2][0], ap2, bp0); ffma2(acc2[2][1], ap2, bp1);
            ffma2(acc2[2][2], ap2, bp2); ffma2(acc2[2][3], ap2, bp3);
            ffma2(acc2[3][0], ap3, bp0); ffma2(acc2[3][1], ap3, bp1);
            ffma2(acc2[3][2], ap3, bp2); ffma2(acc2[3][3], ap3, bp3);
        }
        __syncthreads();
    }

    #pragma unroll
    for (int i = 0; i < 4; i++)
        #pragma unroll
        for (int j = 0; j < 4; j++) {
            float c0, c1; unpack2(acc2[i][j], c0, c1);
            float* dst = &C[(size_t)(ty*4 + i) * N + n0 + tx*8 + 2*j];
            atomicAdd(dst + 0, c0);
            atomicAdd(dst + 1, c1);
        }
}

// ---------------------------------------------------------------------------
// RoPE on g_q and g_k, in place.
// ---------------------------------------------------------------------------
__global__ void rope_kernel(const float* __restrict__ fc, const float* __restrict__ fs) {
    int idx = blockIdx.x * blockDim.x + threadIdx.x;
    const int QP = BB*SS*NHH*64;   // 131072
    const int KP = BB*SS*NKVV*64;  // 32768
    if (idx >= QP + KP) return;

    float* ptr;
    int s, j;
    if (idx < QP) {
        int row = idx >> 11;
        int rem = idx & 2047;
        int h = rem >> 6; j = rem & 63;
        s = row & 15;
        ptr = g_q + (size_t)row * 4096 + h * 128 + j * 2;
    } else {
        int i2 = idx - QP;
        int row = i2 >> 9;
        int rem = i2 & 511;
        int h = rem >> 6; j = rem & 63;
        s = row & 15;
        ptr = g_k + (size_t)row * 1024 + h * 128 + j * 2;
    }
    float c  = fc[s * 64 + j];
    float sn = fs[s * 64 + j];
    float x0 = ptr[0], x1 = ptr[1];
    ptr[0] = x0 * c - x1 * sn;
    ptr[1] = x0 * sn + x1 * c;
}

// ---------------------------------------------------------------------------
// Scores v2: block = (128-key tile, b*8+kvh), 128 threads, dynamic smem.
// Each lane owns 4 DISTINCT keys (tk, +32, +64, +96) -> 4 k-loads amortize
// the 4 q-broadcast loads: crossbar phases per FFMA2 halved vs v1.
// K tile loaded once, reused by the 4 GQA heads.
// ---------------------------------------------------------------------------
#define KS_STRIDE 132
#define SMEM_SCORES ((128*KS_STRIDE + 16*KS_STRIDE) * 4)

extern __shared__ float smem_dyn[];

__global__ __launch_bounds__(128) void scores_kernel(const float* __restrict__ cache_k) {
    float* ks = smem_dyn;                      // [128][132]
    float* qs = smem_dyn + 128 * KS_STRIDE;    // [16][132]

    const int g   = blockIdx.y;          // 0..31  = b*8 + kvh
    const int b   = g >> 3, kvh = g & 7;
    const int l0  = blockIdx.x * 128;

    const int t = threadIdx.x;

    // Stage K tile: 128 keys x 128 d
    #pragma unroll
    for (int r = 0; r < 32; r++) {
        int f = t + r * 128; int i = f >> 5, dq = f & 31;
        int l = l0 + i;
        float4 v = make_float4(0.f, 0.f, 0.f, 0.f);
        if (l < STARTP)
            v = *(const float4*)&cache_k[(((size_t)b * MAXPP + l) * NKVV + kvh) * HDD + dq * 4];
        else if (l < LCTX)
            v = *(const float4*)&g_k[(size_t)(b*16 + (l - STARTP)) * 1024 + kvh * 128 + dq * 4];
        *(float4*)&ks[i * KS_STRIDE + dq * 4] = v;
    }

    const int tq = t >> 5;       // warp id -> 4 query rows each
    const int tk = t & 31;       // keys tk, tk+32, tk+64, tk+96
    const float sc = 0.08838834764831845f;  // 1/sqrt(128)

    for (int hl = 0; hl < 4; hl++) {
        const int h = kvh * 4 + hl;
        __syncthreads();   // hl=0: ks visible; hl>0: prior compute done before qs overwrite
        #pragma unroll
        for (int r = 0; r < 4; r++) {
            int f = t + r * 128; int s = f >> 5, dq = f & 31;
            *(float4*)&qs[s * KS_STRIDE + dq * 4] =
                *(const float4*)&g_q[(size_t)(b*16 + s) * 4096 + h * 128 + dq * 4];
        }
        __syncthreads();

        ull acc[4][4];   // [q row][key j]
        #pragma unroll
        for (int i = 0; i < 4; i++)
            #pragma unroll
            for (int j = 0; j < 4; j++) acc[i][j] = 0ull;

        #pragma unroll 4
        for (int d = 0; d < 128; d += 4) {
            float4 k0 = *(const float4*)&ks[(tk      ) * KS_STRIDE + d];
            float4 k1 = *(const float4*)&ks[(tk + 32 ) * KS_STRIDE + d];
            float4 k2 = *(const float4*)&ks[(tk + 64 ) * KS_STRIDE + d];
            float4 k3 = *(const float4*)&ks[(tk + 96 ) * KS_STRIDE + d];
            ull k0a = pack2(k0.x, k0.y), k0b = pack2(k0.z, k0.w);
            ull k1a = pack2(k1.x, k1.y), k1b = pack2(k1.z, k1.w);
            ull k2a = pack2(k2.x, k2.y), k2b = pack2(k2.z, k2.w);
            ull k3a = pack2(k3.x, k3.y), k3b = pack2(k3.z, k3.w);
            #pragma unroll
            for (int i = 0; i < 4; i++) {
                float4 q = *(const float4*)&qs[(tq*4 + i) * KS_STRIDE + d];
                ull qa = pack2(q.x, q.y), qb = pack2(q.z, q.w);
                ffma2(acc[i][0], qa, k0a); ffma2(acc[i][0], qb, k0b);
                ffma2(acc[i][1], qa, k1a); ffma2(acc[i][1], qb, k1b);
                ffma2(acc[i][2], qa, k2a); ffma2(acc[i][2], qb, k2b);
                ffma2(acc[i][3], qa, k3a); ffma2(acc[i][3], qb, k3b);
            }
        }

        const int bh = b * 32 + h;
        #pragma unroll
        for (int i = 0; i < 4; i++) {
            size_t rb = ((size_t)bh * 16 + tq*4 + i) * LCTX;
            #pragma unroll
            for (int j = 0; j < 4; j++) {
                int l = l0 + tk + 32*j;
                float lo, hi; unpack2(acc[i][j], lo, hi);
                if (l < LCTX) g_scores[rb + l] = (lo + hi) * sc;
            }
        }
    }
}

// ---------------------------------------------------------------------------
// Row softmax over L=2064, one block (256 threads) per (b,h,s) row.
// ---------------------------------------------------------------------------
__global__ __launch_bounds__(256) void softmax_kernel() {
    const int row = blockIdx.x;           // 0..2047
    float* p = g_scores + (size_t)row * LCTX;
    const int t = threadIdx.x;
    __shared__ float red[8];

    float vals[9];
    int nv = 0;
    float m = -1e30f;
    for (int i = t; i < LCTX; i += 256) { float v = p[i]; vals[nv++] = v; m = fmaxf(m, v); }

    #pragma unroll
    for (int o = 16; o; o >>= 1) m = fmaxf(m, __shfl_xor_sync(0xffffffffu, m, o));
    if ((t & 31) == 0) red[t >> 5] = m;
    __syncthreads();
    float mm = red[0];
    #pragma unroll
    for (int w = 1; w < 8; w++) mm = fmaxf(mm, red[w]);
    __syncthreads();

    float sum = 0.f;
    for (int j = 0; j < nv; j++) { vals[j] = __expf(vals[j] - mm); sum += vals[j]; }
    #pragma unroll
    for (int o = 16; o; o >>= 1) sum += __shfl_xor_sync(0xffffffffu, sum, o);
    if ((t & 31) == 0) red[t >> 5] = sum;
    __syncthreads();
    float tot = 0.f;
    #pragma unroll
    for (int w = 0; w < 8; w++) tot += red[w];

    float inv = 1.0f / tot;
    nv = 0;
    for (int i = t; i < LCTX; i += 256) p[i] = vals[nv++] * inv;
}

// ---------------------------------------------------------------------------
// PV v2: block = (split 0..10, b*8+kvh). V float4 loaded ONCE per l and
// reused by all 4 GQA heads in the same inner loop; P via cheap scalar
// broadcasts from a 4-head smem tile. Atomic accumulation into g_attn.
// ---------------------------------------------------------------------------
__global__ __launch_bounds__(128) void pv_kernel(const float* __restrict__ cache_v) {
    const int g = blockIdx.y;            // b*8 + kvh
    const int b = g >> 3, kvh = g & 7;
    const int split = blockIdx.x;        // 0..10

    __shared__ float Vs[64][128];        // row access has fixed row per warp-instr -> no pad needed
    __shared__ float Ps[4*16*64];        // [head][s][l], scalar broadcast reads

    const int t = threadIdx.x;
    const int sg = t >> 5, dg = t & 31;  // 4 query rows per warp, float4 of d per lane

    ull acc2[4][4][2];                   // [head][q][d-pair]
    #pragma unroll
    for (int hl = 0; hl < 4; hl++)
        #pragma unroll
        for (int i = 0; i < 4; i++) { acc2[hl][i][0] = 0ull; acc2[hl][i][1] = 0ull; }

    for (int tt = split * 3; tt < split * 3 + 3; tt++) {
        const int l0 = tt * 64;
        __syncthreads();                 // prior compute done before Vs/Ps overwrite
        // V tile: 64 l x 128 d
        #pragma unroll
        for (int r = 0; r < 16; r++) {
            int f = t + r * 128; int i = f >> 5, dq = f & 31;
            int l = l0 + i;
            float4 v = make_float4(0.f, 0.f, 0.f, 0.f);
            if (l < STARTP)
                v = *(const float4*)&cache_v[(((size_t)b * MAXPP + l) * NKVV + kvh) * HDD + dq * 4];
            else if (l < LCTX)
                v = *(const float4*)&g_v[(size_t)(b*16 + (l - STARTP)) * 1024 + kvh * 128 + dq * 4];
            *(float4*)&Vs[i][dq*4] = v;
        }
        // P tile: 4 heads x 16 s x 64 l
        #pragma unroll
        for (int r = 0; r < 8; r++) {
            int f = t + r * 128;
            int sh = f >> 4;             // 0..63 = hl*16 + s
            int hl = sh >> 4, s = sh & 15;
            int lq = f & 15;
            int l = l0 + lq * 4;
            const int bh = b * 32 + kvh * 4 + hl;
            float4 v = make_float4(0.f, 0.f, 0.f, 0.f);
            if (l < LCTX)   // LCTX % 4 == 0: float4 fully valid or fully OOB
                v = *(const float4*)&g_scores[((size_t)bh * 16 + s) * LCTX + l];
            *(float4*)&Ps[(hl * 16 + s) * 64 + lq * 4] = v;
        }
        __syncthreads();

        #pragma unroll 2
        for (int l = 0; l < 64; l++) {
            ull v01 = *(const ull*)&Vs[l][dg*4];
            ull v23 = *(const ull*)&Vs[l][dg*4 + 2];
            #pragma unroll
            for (int hl = 0; hl < 4; hl++) {
                #pragma unroll
                for (int i = 0; i < 4; i++) {
                    float pp = Ps[(hl * 16 + sg*4 + i) * 64 + l];
                    ull p2 = pack2(pp, pp);
                    ffma2(acc2[hl][i][0], p2, v01);
                    ffma2(acc2[hl][i][1], p2, v23);
                }
            }
        }
    }

    #pragma unroll
    for (int hl = 0; hl < 4; hl++) {
        const int h = kvh * 4 + hl;
        #pragma unroll
        for (int i = 0; i < 4; i++) {
            int s = sg * 4 + i;
            float* dst = &g_attn[(size_t)(b*16 + s) * 4096 + h * 128 + dg * 4];
            float c0, c1;
            unpack2(acc2[hl][i][0], c0, c1);
            atomicAdd(dst + 0, c0);
            atomicAdd(dst + 1, c1);
            unpack2(acc2[hl][i][1], c0, c1);
            atomicAdd(dst + 2, c0);
            atomicAdd(dst + 3, c1);
        }
    }
}

// ---------------------------------------------------------------------------
// Launch
// ---------------------------------------------------------------------------
extern "C" void kernel_launch(void* const* d_in, const int* in_sizes, int n_in,
                              void* d_out, int out_size) {
    const float* x       = (const float*)d_in[0];
    const float* fc      = (const float*)d_in[1];
    const float* fs      = (const float*)d_in[2];
    const float* cache_k = (const float*)d_in[3];
    const float* cache_v = (const float*)d_in[4];
    const float* Wq      = (const float*)d_in[5];
    const float* Wk      = (const float*)d_in[6];
    const float* Wv      = (const float*)d_in[7];
    const float* Wo      = (const float*)d_in[8];
    float* out = (float*)d_out;
    (void)in_sizes; (void)n_in; (void)out_size;

    static bool attr_done = false;
    if (!attr_done) {
        cudaFuncSetAttribute(scores_kernel,
                             cudaFuncAttributeMaxDynamicSharedMemorySize, SMEM_SCORES);
        attr_done = true;
    }

    zero_kernel<<<1024, 256>>>(out);

    // Fused QKV projections (split-K=16, atomic accumulate): 48x16 = 768 blocks
    gemm64<<<dim3(48, SPLITK), 256>>>(x, Wq, Wk, Wv, nullptr, 0);

    rope_kernel<<<640, 256>>>(fc, fs);

    scores_kernel<<<dim3(17, 32), 128, SMEM_SCORES>>>(cache_k);
    softmax_kernel<<<2048, 256>>>();
    pv_kernel<<<dim3(11, 32), 128>>>(cache_v);

    // Output projection -> d_out: 32x16 = 512 blocks
    gemm64<<<dim3(32, SPLITK), 256>>>(nullptr, Wo, nullptr, nullptr, out, 1);
}

// round 11
// speedup vs baseline: 1.0419x; 1.0419x over previous
#include <cuda_runtime.h>
#include <math.h>

// Problem constants (shapes fixed by the reference)
#define BB    4
#define SS    16
#define DIMM  4096
#define NHH   32
#define NKVV  8
#define HDD   128
#define MAXPP 4096
#define STARTP 2048
#define LCTX  2064   // STARTP + SS
#define SPLITK 16
#define KCHUNK (DIMM / SPLITK)   // 256 -> 16 BK=16 iterations per block

typedef unsigned long long ull;

// ---------------------------------------------------------------------------
// Packed f32x2 helpers (B300 FFMA2 path — only reachable via explicit PTX)
// ---------------------------------------------------------------------------
__device__ __forceinline__ ull pack2(float lo, float hi) {
    ull r; asm("mov.b64 %0, {%1, %2};" : "=l"(r) : "f"(lo), "f"(hi)); return r;
}
__device__ __forceinline__ void ffma2(ull &d, ull a, ull b) {
    asm("fma.rn.f32x2 %0, %1, %2, %0;" : "+l"(d) : "l"(a), "l"(b));
}
__device__ __forceinline__ void unpack2(ull v, float &lo, float &hi) {
    asm("mov.b64 {%0, %1}, %2;" : "=f"(lo), "=f"(hi) : "l"(v));
}

// ---------------------------------------------------------------------------
// Device scratch (no allocations allowed)
// ---------------------------------------------------------------------------
__device__ float g_q[BB*SS*NHH*HDD];        // row=(b*16+s), col=h*128+d
__device__ float g_k[BB*SS*NKVV*HDD];       // row=(b*16+s), col=kvh*128+d
__device__ float g_v[BB*SS*NKVV*HDD];
__device__ float g_scores[(size_t)BB*NHH*SS*LCTX]; // ~17MB
__device__ float g_attn[BB*SS*NHH*HDD];     // row=(b*16+s), col=h*128+d

// ---------------------------------------------------------------------------
// Zero scratch + output (GEMM/PV accumulate with atomics)
// ---------------------------------------------------------------------------
__global__ void zero_kernel(float* __restrict__ dout) {
    int i = blockIdx.x * blockDim.x + threadIdx.x;   // grid covers 262144
    if (i < BB*SS*NHH*HDD) { g_q[i] = 0.f; g_attn[i] = 0.f; dout[i] = 0.f; }
    if (i < BB*SS*NKVV*HDD) { g_k[i] = 0.f; g_v[i] = 0.f; }
}

// ---------------------------------------------------------------------------
// Tiled fp32 GEMM with split-K=16, register double-buffering, FFMA2.
// C[64 x N] += A[64 x 4096] * W[4096 x N]
// mode 0: fused QKV (bx<32 -> Wq->g_q, bx<40 -> Wk->g_k, else Wv->g_v), A=x
// mode 1: Wo -> d_out, A=g_attn
// ---------------------------------------------------------------------------
__global__ __launch_bounds__(256) void gemm64(
    const float* __restrict__ Aext,
    const float* __restrict__ W0, const float* __restrict__ W1,
    const float* __restrict__ W2,
    float* __restrict__ Cout, int mode)
{
    const float* A; const float* W; float* C; int N, n0;
    const int bx = blockIdx.x;
    if (mode == 0) {
        A = Aext;
        if (bx < 32)      { W = W0; C = g_q; N = 4096; n0 = bx * 128; }
        else if (bx < 40) { W = W1; C = g_k; N = 1024; n0 = (bx - 32) * 128; }
        else              { W = W2; C = g_v; N = 1024; n0 = (bx - 40) * 128; }
    } else {
        A = g_attn; W = W0; C = Cout; N = 4096; n0 = bx * 128;
    }
    const int k0 = blockIdx.y * KCHUNK;

    __shared__ float As[16][64];
    __shared__ float Bs[16][128];

    const int t  = threadIdx.x;
    const int tx = t & 15, ty = t >> 4;
    const int arow = t >> 2, akq = t & 3;
    const int f0 = t * 2, f1 = t * 2 + 1;
    const int kr0 = f0 >> 5, nq0 = f0 & 31;
    const int kr1 = f1 >> 5, nq1 = f1 & 31;

    ull acc2[4][4];
    #pragma unroll
    for (int i = 0; i < 4; i++)
        #pragma unroll
        for (int j = 0; j < 4; j++) acc2[i][j] = 0ull;

    // Prologue: preload first tile into registers
    float4 aN = *(const float4*)(A + (size_t)arow * DIMM + k0 + akq * 4);
    float4 bN0 = *(const float4*)(W + (size_t)(k0 + kr0) * N + n0 + nq0 * 4);
    float4 bN1 = *(const float4*)(W + (size_t)(k0 + kr1) * N + n0 + nq1 * 4);

    #pragma unroll 1
    for (int it = 0; it < KCHUNK / 16; it++) {
        As[akq*4+0][arow] = aN.x;
        As[akq*4+1][arow] = aN.y;
        As[akq*4+2][arow] = aN.z;
        As[akq*4+3][arow] = aN.w;
        *(float4*)&Bs[kr0][nq0*4] = bN0;
        *(float4*)&Bs[kr1][nq1*4] = bN1;
        __syncthreads();

        if (it + 1 < KCHUNK / 16) {   // overlap next tile's gmem loads with compute
            const int kk = k0 + (it + 1) * 16;
            aN  = *(const float4*)(A + (size_t)arow * DIMM + kk + akq * 4);
            bN0 = *(const float4*)(W + (size_t)(kk + kr0) * N + n0 + nq0 * 4);
            bN1 = *(const float4*)(W + (size_t)(kk + kr1) * N + n0 + nq1 * 4);
        }

        #pragma unroll
        for (int k = 0; k < 16; k++) {
            float4 a  = *(const float4*)&As[k][ty*4];
            float4 b0 = *(const float4*)&Bs[k][tx*8];
            float4 b1 = *(const float4*)&Bs[k][tx*8+4];
            ull bp0 = pack2(b0.x, b0.y), bp1 = pack2(b0.z, b0.w);
            ull bp2 = pack2(b1.x, b1.y), bp3 = pack2(b1.z, b1.w);
            ull ap0 = pack2(a.x, a.x), ap1 = pack2(a.y, a.y);
            ull ap2 = pack2(a.z, a.z), ap3 = pack2(a.w, a.w);
            ffma2(acc2[0][0], ap0, bp0); ffma2(acc2[0][1], ap0, bp1);
            ffma2(acc2[0][2], ap0, bp2); ffma2(acc2[0][3], ap0, bp3);
            ffma2(acc2[1][0], ap1, bp0); ffma2(acc2[1][1], ap1, bp1);
            ffma2(acc2[1][2], ap1, bp2); ffma2(acc2[1][3], ap1, bp3);
            ffma2(acc2[2][0], ap2, bp0); ffma2(acc2[2][1], ap2, bp1);
            ffma2(acc2[2][2], ap2, bp2); ffma2(acc2[2][3], ap2, bp3);
            ffma2(acc2[3][0], ap3, bp0); ffma2(acc2[3][1], ap3, bp1);
            ffma2(acc2[3][2], ap3, bp2); ffma2(acc2[3][3], ap3, bp3);
        }
        __syncthreads();
    }

    #pragma unroll
    for (int i = 0; i < 4; i++)
        #pragma unroll
        for (int j = 0; j < 4; j++) {
            float c0, c1; unpack2(acc2[i][j], c0, c1);
            float* dst = &C[(size_t)(ty*4 + i) * N + n0 + tx*8 + 2*j];
            atomicAdd(dst + 0, c0);
            atomicAdd(dst + 1, c1);
        }
}

// ---------------------------------------------------------------------------
// RoPE on g_q and g_k, in place.
// ---------------------------------------------------------------------------
__global__ void rope_kernel(const float* __restrict__ fc, const float* __restrict__ fs) {
    int idx = blockIdx.x * blockDim.x + threadIdx.x;
    const int QP = BB*SS*NHH*64;   // 131072
    const int KP = BB*SS*NKVV*64;  // 32768
    if (idx >= QP + KP) return;

    float* ptr;
    int s, j;
    if (idx < QP) {
        int row = idx >> 11;
        int rem = idx & 2047;
        int h = rem >> 6; j = rem & 63;
        s = row & 15;
        ptr = g_q + (size_t)row * 4096 + h * 128 + j * 2;
    } else {
        int i2 = idx - QP;
        int row = i2 >> 9;
        int rem = i2 & 511;
        int h = rem >> 6; j = rem & 63;
        s = row & 15;
        ptr = g_k + (size_t)row * 1024 + h * 128 + j * 2;
    }
    float c  = fc[s * 64 + j];
    float sn = fs[s * 64 + j];
    float x0 = ptr[0], x1 = ptr[1];
    ptr[0] = x0 * c - x1 * sn;
    ptr[1] = x0 * sn + x1 * c;
}

// ---------------------------------------------------------------------------
// Scores v3: block = (64-key tile, b*8+kvh), 256 threads, all 4 GQA heads.
// Warp w -> head (w>>1), q rows ((w&1)*8 .. +7); lane -> keys tk, tk+32.
// Crossbar phases (4*nk + nq = 16) == FFMA2 issue cycles (nq*nk = 16):
// balanced pipes. K + all-head Q staged once; a single __syncthreads.
// smem = 128 rows * 132 * 4B = 67.6KB dynamic -> 3 blocks/SM (24 warps).
// ---------------------------------------------------------------------------
#define KS_STRIDE 132
#define SMEM_SCORES ((64 + 64) * KS_STRIDE * 4)

extern __shared__ float smem_dyn[];

__global__ __launch_bounds__(256) void scores_kernel(const float* __restrict__ cache_k) {
    float* ks = smem_dyn;                     // [64 keys][132]
    float* qs = smem_dyn + 64 * KS_STRIDE;    // [4 heads * 16 s][132]

    const int g   = blockIdx.y;          // 0..31  = b*8 + kvh
    const int b   = g >> 3, kvh = g & 7;
    const int l0  = blockIdx.x * 64;

    const int t = threadIdx.x;

    // Stage K tile: 64 keys x 128 d  (8 float4 per thread)
    #pragma unroll
    for (int r = 0; r < 8; r++) {
        int f = t + r * 256; int i = f >> 5, dq = f & 31;
        int l = l0 + i;
        float4 v = make_float4(0.f, 0.f, 0.f, 0.f);
        if (l < STARTP)
            v = *(const float4*)&cache_k[(((size_t)b * MAXPP + l) * NKVV + kvh) * HDD + dq * 4];
        else if (l < LCTX)
            v = *(const float4*)&g_k[(size_t)(b*16 + (l - STARTP)) * 1024 + kvh * 128 + dq * 4];
        *(float4*)&ks[i * KS_STRIDE + dq * 4] = v;
    }
    // Stage Q for all 4 heads: 64 rows x 128 d
    #pragma unroll
    for (int r = 0; r < 8; r++) {
        int f = t + r * 256;
        int row = f >> 5;                // hl*16 + s
        int hl = row >> 4, s = row & 15;
        int dq = f & 31;
        *(float4*)&qs[row * KS_STRIDE + dq * 4] =
            *(const float4*)&g_q[(size_t)(b*16 + s) * 4096 + (kvh*4 + hl) * 128 + dq * 4];
    }
    __syncthreads();

    const int w  = t >> 5;               // warp 0..7
    const int tk = t & 31;               // keys tk, tk+32
    const int hl = w >> 1;               // head within GQA group
    const int q0 = (w & 1) * 8;          // 8 q rows per warp
    const float* qbase = qs + (hl * 16 + q0) * KS_STRIDE;
    const float sc = 0.08838834764831845f;  // 1/sqrt(128)

    ull acc[8][2];
    #pragma unroll
    for (int i = 0; i < 8; i++) { acc[i][0] = 0ull; acc[i][1] = 0ull; }

    #pragma unroll 4
    for (int d = 0; d < 128; d += 4) {
        float4 k0 = *(const float4*)&ks[tk * KS_STRIDE + d];
        float4 k1 = *(const float4*)&ks[(tk + 32) * KS_STRIDE + d];
        ull k0a = pack2(k0.x, k0.y), k0b = pack2(k0.z, k0.w);
        ull k1a = pack2(k1.x, k1.y), k1b = pack2(k1.z, k1.w);
        #pragma unroll
        for (int i = 0; i < 8; i++) {
            float4 q = *(const float4*)&qbase[i * KS_STRIDE + d];
            ull qa = pack2(q.x, q.y), qb = pack2(q.z, q.w);
            ffma2(acc[i][0], qa, k0a); ffma2(acc[i][0], qb, k0b);
            ffma2(acc[i][1], qa, k1a); ffma2(acc[i][1], qb, k1b);
        }
    }

    const int bh = b * 32 + kvh * 4 + hl;
    const int la = l0 + tk, lb = l0 + tk + 32;
    #pragma unroll
    for (int i = 0; i < 8; i++) {
        size_t rb = ((size_t)bh * 16 + q0 + i) * LCTX;
        float lo, hi;
        unpack2(acc[i][0], lo, hi); if (la < LCTX) g_scores[rb + la] = (lo + hi) * sc;
        unpack2(acc[i][1], lo, hi); if (lb < LCTX) g_scores[rb + lb] = (lo + hi) * sc;
    }
}

// ---------------------------------------------------------------------------
// Row softmax over L=2064, one block (256 threads) per (b,h,s) row.
// ---------------------------------------------------------------------------
__global__ __launch_bounds__(256) void softmax_kernel() {
    const int row = blockIdx.x;           // 0..2047
    float* p = g_scores + (size_t)row * LCTX;
    const int t = threadIdx.x;
    __shared__ float red[8];

    float vals[9];
    int nv = 0;
    float m = -1e30f;
    for (int i = t; i < LCTX; i += 256) { float v = p[i]; vals[nv++] = v; m = fmaxf(m, v); }

    #pragma unroll
    for (int o = 16; o; o >>= 1) m = fmaxf(m, __shfl_xor_sync(0xffffffffu, m, o));
    if ((t & 31) == 0) red[t >> 5] = m;
    __syncthreads();
    float mm = red[0];
    #pragma unroll
    for (int w = 1; w < 8; w++) mm = fmaxf(mm, red[w]);
    __syncthreads();

    float sum = 0.f;
    for (int j = 0; j < nv; j++) { vals[j] = __expf(vals[j] - mm); sum += vals[j]; }
    #pragma unroll
    for (int o = 16; o; o >>= 1) sum += __shfl_xor_sync(0xffffffffu, sum, o);
    if ((t & 31) == 0) red[t >> 5] = sum;
    __syncthreads();
    float tot = 0.f;
    #pragma unroll
    for (int w = 0; w < 8; w++) tot += red[w];

    float inv = 1.0f / tot;
    nv = 0;
    for (int i = t; i < LCTX; i += 256) p[i] = vals[nv++] * inv;
}

// ---------------------------------------------------------------------------
// PV (R5 configuration): block = (split 0..10, b*8+kvh). Each split does 3
// of the 33 64-key tiles. V tile loaded once per tile, reused by 4 GQA heads.
// ---------------------------------------------------------------------------
__global__ __launch_bounds__(128) void pv_kernel(const float* __restrict__ cache_v) {
    const int g = blockIdx.y;            // b*8 + kvh
    const int b = g >> 3, kvh = g & 7;
    const int split = blockIdx.x;        // 0..10

    __shared__ float Vs[64][128];
    __shared__ float Ps[16][64];

    const int t = threadIdx.x;
    const int sg = t >> 5, dg = t & 31;  // 4 query rows, float4 of d each

    ull acc2[4][4][2];                   // [head][q][d-pair]
    #pragma unroll
    for (int hl = 0; hl < 4; hl++)
        #pragma unroll
        for (int i = 0; i < 4; i++) { acc2[hl][i][0] = 0ull; acc2[hl][i][1] = 0ull; }

    for (int tt = split * 3; tt < split * 3 + 3; tt++) {
        const int l0 = tt * 64;
        __syncthreads();                 // prior compute done before Vs/Ps overwrite
        #pragma unroll
        for (int r = 0; r < 16; r++) {
            int f = t + r * 128; int i = f >> 5, dq = f & 31;
            int l = l0 + i;
            float4 v = make_float4(0.f, 0.f, 0.f, 0.f);
            if (l < STARTP)
                v = *(const float4*)&cache_v[(((size_t)b * MAXPP + l) * NKVV + kvh) * HDD + dq * 4];
            else if (l < LCTX)
                v = *(const float4*)&g_v[(size_t)(b*16 + (l - STARTP)) * 1024 + kvh * 128 + dq * 4];
            *(float4*)&Vs[i][dq*4] = v;
        }

        for (int hl = 0; hl < 4; hl++) {
            if (hl) __syncthreads();     // prev head compute done before Ps overwrite
            const int bh = b * 32 + kvh * 4 + hl;
            #pragma unroll
            for (int r = 0; r < 2; r++) {
                int f = t + r * 128; int s = f >> 4, lq = f & 15;
                int l = l0 + lq * 4;
                float4 v = make_float4(0.f, 0.f, 0.f, 0.f);
                if (l < LCTX)   // LCTX % 4 == 0
                    v = *(const float4*)&g_scores[((size_t)bh * 16 + s) * LCTX + l];
                *(float4*)&Ps[s][lq*4] = v;
            }
            __syncthreads();

            #pragma unroll 4
            for (int l = 0; l < 64; l++) {
                ull v01 = *(const ull*)&Vs[l][dg*4];
                ull v23 = *(const ull*)&Vs[l][dg*4 + 2];
                #pragma unroll
                for (int i = 0; i < 4; i++) {
                    float pp = Ps[sg*4 + i][l];
                    ull p2 = pack2(pp, pp);
                    ffma2(acc2[hl][i][0], p2, v01);
                    ffma2(acc2[hl][i][1], p2, v23);
                }
            }
        }
    }

    #pragma unroll
    for (int hl = 0; hl < 4; hl++) {
        const int h = kvh * 4 + hl;
        #pragma unroll
        for (int i = 0; i < 4; i++) {
            int s = sg * 4 + i;
            float* dst = &g_attn[(size_t)(b*16 + s) * 4096 + h * 128 + dg * 4];
            float c0, c1;
            unpack2(acc2[hl][i][0], c0, c1);
            atomicAdd(dst + 0, c0);
            atomicAdd(dst + 1, c1);
            unpack2(acc2[hl][i][1], c0, c1);
            atomicAdd(dst + 2, c0);
            atomicAdd(dst + 3, c1);
        }
    }
}

// ---------------------------------------------------------------------------
// Launch
// ---------------------------------------------------------------------------
extern "C" void kernel_launch(void* const* d_in, const int* in_sizes, int n_in,
                              void* d_out, int out_size) {
    const float* x       = (const float*)d_in[0];
    const float* fc      = (const float*)d_in[1];
    const float* fs      = (const float*)d_in[2];
    const float* cache_k = (const float*)d_in[3];
    const float* cache_v = (const float*)d_in[4];
    const float* Wq      = (const float*)d_in[5];
    const float* Wk      = (const float*)d_in[6];
    const float* Wv      = (const float*)d_in[7];
    const float* Wo      = (const float*)d_in[8];
    float* out = (float*)d_out;
    (void)in_sizes; (void)n_in; (void)out_size;

    cudaFuncSetAttribute(scores_kernel,
                         cudaFuncAttributeMaxDynamicSharedMemorySize, SMEM_SCORES);

    zero_kernel<<<1024, 256>>>(out);

    // Fused QKV projections (split-K=16, atomic accumulate): 48x16 = 768 blocks
    gemm64<<<dim3(48, SPLITK), 256>>>(x, Wq, Wk, Wv, nullptr, 0);

    rope_kernel<<<640, 256>>>(fc, fs);

    scores_kernel<<<dim3(33, 32), 256, SMEM_SCORES>>>(cache_k);
    softmax_kernel<<<2048, 256>>>();
    pv_kernel<<<dim3(11, 32), 128>>>(cache_v);

    // Output projection -> d_out: 32x16 = 512 blocks
    gemm64<<<dim3(32, SPLITK), 256>>>(nullptr, Wo, nullptr, nullptr, out, 1);
}